// round 10
// baseline (speedup 1.0000x reference)
#include <cuda_runtime.h>
#include <cstdint>

// ForgetMult fused single-pass chunked scan — persistent blocks, 2-stage
// cp.async pipeline, decoupled lookback.
// h_t = f_t*x_t + (1-f_t)*h_{t-1}  ==  h_t = h_{t-1} + f_t*(x_t - h_{t-1})
//
// 148 persistent blocks (1/SM, co-resident) stride chunk-major over
// (chunk, tile) items. Per item: prefetch NEXT item's 64 KB tile via cp.async
// while processing the current one from smem (summary -> lookback -> forward
// recurrence -> streamed stores). Lookback waits overlap with prefetch, so
// DRAM stays busy while the 32 independent per-tile chains propagate.

#define FM_SEQ     2048
#define FM_NCH     16384
#define FM_NG      (FM_NCH / 2)              // 8192 float2 channel-groups
#define FM_L       16                        // timesteps per chunk
#define FM_NCHUNKS (FM_SEQ / FM_L)           // 128
#define FM_TPB     256                       // threads/block == groups per tile
#define FM_NTILES  (FM_NG / FM_TPB)          // 32
#define FM_NITEMS  (FM_NCHUNKS * FM_NTILES)  // 4096
#define FM_GRID    148                       // <= SM count; all co-resident

#define FM_ARR_BYTES   (FM_L * FM_TPB * 8)       // one array, one stage: 32 KB
#define FM_STAGE_BYTES (2 * FM_ARR_BYTES)        // sf + sx: 64 KB
#define FM_SMEM        (2 * FM_STAGE_BYTES)      // 2 stages: 128 KB

// Scratch (allocation-free rule: __device__ globals). 3 x 8 MB + flags.
__device__ float2 g_pa[FM_NCHUNKS][FM_NG];
__device__ float2 g_pb[FM_NCHUNKS][FM_NG];
__device__ float2 g_inc[FM_NCHUNKS][FM_NG];
__device__ int    g_flag[FM_NCHUNKS][FM_NTILES];  // 0=none, 1=partial, 2=inclusive

__global__ void fm_init_flags()
{
    int i = blockIdx.x * blockDim.x + threadIdx.x;
    if (i < FM_NCHUNKS * FM_NTILES) ((int*)g_flag)[i] = 0;
}

__device__ __forceinline__ void cp_async8(void* s, const void* g)
{
    uint32_t sa = (uint32_t)__cvta_generic_to_shared(s);
    asm volatile("cp.async.ca.shared.global [%0], [%1], 8;\n" :: "r"(sa), "l"(g));
}

__global__ __launch_bounds__(FM_TPB, 1) void fm_fused(
    const float2* __restrict__ f, const float2* __restrict__ x,
    const float2* __restrict__ h0, float2* __restrict__ out)
{
    extern __shared__ char smem[];
    __shared__ int s_stop;

    const int tid = threadIdx.x;

    // Issue prefetch of item `wi` into stage `st`.
    auto prefetch = [&](int wi, int st) {
        const int chunk = wi / FM_NTILES;
        const int tile  = wi % FM_NTILES;
        const int g     = tile * FM_TPB + tid;
        const size_t base = (size_t)chunk * FM_L * FM_NG + g;
        float2* sf = (float2*)(smem + st * FM_STAGE_BYTES);
        float2* sx = (float2*)(smem + st * FM_STAGE_BYTES + FM_ARR_BYTES);
#pragma unroll
        for (int t = 0; t < FM_L; t++) {
            cp_async8(&sf[t * FM_TPB + tid], f + base + (size_t)t * FM_NG);
            cp_async8(&sx[t * FM_TPB + tid], x + base + (size_t)t * FM_NG);
        }
        asm volatile("cp.async.commit_group;\n" ::: "memory");
    };

    int wi = blockIdx.x;
    if (wi >= FM_NITEMS) return;

    prefetch(wi, 0);
    int stage = 0;

    for (; wi < FM_NITEMS; wi += FM_GRID) {
        const int next = wi + FM_GRID;
        if (next < FM_NITEMS) {
            prefetch(next, stage ^ 1);
            asm volatile("cp.async.wait_group 1;\n" ::: "memory");
        } else {
            asm volatile("cp.async.wait_group 0;\n" ::: "memory");
        }

        const int chunk = wi / FM_NTILES;
        const int tile  = wi % FM_NTILES;
        const int g     = tile * FM_TPB + tid;
        const size_t base = (size_t)chunk * FM_L * FM_NG + g;
        const float2* sf = (const float2*)(smem + stage * FM_STAGE_BYTES);
        const float2* sx = (const float2*)(smem + stage * FM_STAGE_BYTES + FM_ARR_BYTES);

        // ---- Chunk summary: a = prod(1-f), b = local scan from 0.
        // (Each thread reads only the smem slots it wrote -> no barrier.)
        float2 a = make_float2(1.f, 1.f);
        float2 b = make_float2(0.f, 0.f);
#pragma unroll
        for (int t = 0; t < FM_L; t++) {
            const float2 ft = sf[t * FM_TPB + tid];
            const float2 xt = sx[t * FM_TPB + tid];
            b.x = fmaf(ft.x, xt.x - b.x, b.x);  a.x *= (1.f - ft.x);
            b.y = fmaf(ft.y, xt.y - b.y, b.y);  a.y *= (1.f - ft.y);
        }

        // ---- Resolve h_start via decoupled lookback (parallel probe).
        float2 hstart;
        if (chunk == 0) {
            hstart = __ldg(h0 + g);
        } else {
            g_pa[chunk][g] = a;
            g_pb[chunk][g] = b;
            __threadfence();
            __syncthreads();
            if (tid == 0) atomicExch(&g_flag[chunk][tile], 1);

            // Threads 0..31 probe chunk-1-tid; nearest flag==2 wins.
            const int myj = chunk - 1 - tid;
            int stop;
            for (;;) {
                if (tid == 0) s_stop = -1;
                __syncthreads();
                if (tid < 32 && myj >= 0) {
                    int s;
                    do {
                        s = *(volatile int*)&g_flag[myj][tile];
                        if (s == 0) __nanosleep(64);
                    } while (s == 0);
                    if (s == 2) atomicMax(&s_stop, myj);
                }
                __syncthreads();
                stop = s_stop;
                if (stop >= 0) break;
            }
            __threadfence();

            // Compose partials (stop+1 .. chunk-1) onto h_end(stop).
            float2 h = g_inc[stop][g];
            for (int j = stop + 1; j < chunk; j++) {
                const float2 aj = g_pa[j][g];
                const float2 bj = g_pb[j][g];
                h.x = fmaf(aj.x, h.x, bj.x);
                h.y = fmaf(aj.y, h.y, bj.y);
            }
            hstart = h;
        }

        // ---- Publish inclusive state ASAP (successors are spinning on it).
        if (chunk < FM_NCHUNKS - 1) {
            float2 he;
            he.x = fmaf(a.x, hstart.x, b.x);
            he.y = fmaf(a.y, hstart.y, b.y);
            g_inc[chunk][g] = he;
            __threadfence();
            __syncthreads();
            if (tid == 0) atomicExch(&g_flag[chunk][tile], 2);
        }

        // ---- Output: exact forward recurrence from smem, streamed stores.
        float2 h = hstart;
#pragma unroll
        for (int t = 0; t < FM_L; t++) {
            const float2 ft = sf[t * FM_TPB + tid];
            const float2 xt = sx[t * FM_TPB + tid];
            h.x = fmaf(ft.x, xt.x - h.x, h.x);
            h.y = fmaf(ft.y, xt.y - h.y, h.y);
            __stcs(out + base + (size_t)t * FM_NG, h);
        }

        stage ^= 1;
        __syncthreads();   // protect s_stop / stage reuse across iterations
    }
}

// ---------------- Fallback: naive per-channel scan (unexpected shapes) ----------------
__global__ void fm_naive(const float* __restrict__ f, const float* __restrict__ x,
                         const float* __restrict__ h0, float* __restrict__ out,
                         int seq, int nch)
{
    int c = blockIdx.x * blockDim.x + threadIdx.x;
    if (c >= nch) return;
    float h = h0[c];
    for (int t = 0; t < seq; t++) {
        const float ft = f[(size_t)t * nch + c];
        h = fmaf(1.f - ft, h, ft * x[(size_t)t * nch + c]);
        out[(size_t)t * nch + c] = h;
    }
}

extern "C" void kernel_launch(void* const* d_in, const int* in_sizes, int n_in,
                              void* d_out, int out_size)
{
    const float* f  = (const float*)d_in[0];
    const float* x  = (const float*)d_in[1];
    const float* h0 = (const float*)d_in[2];
    float* out      = (float*)d_out;

    const int nch = in_sizes[2];
    const int seq = in_sizes[0] / nch;

    if (seq == FM_SEQ && nch == FM_NCH) {
        cudaFuncSetAttribute(fm_fused, cudaFuncAttributeMaxDynamicSharedMemorySize,
                             FM_SMEM);
        fm_init_flags<<<(FM_NITEMS + 255) / 256, 256>>>();
        fm_fused<<<FM_GRID, FM_TPB, FM_SMEM>>>(
            (const float2*)f, (const float2*)x, (const float2*)h0, (float2*)out);
    } else {
        int tpb = 128;
        fm_naive<<<(nch + tpb - 1) / tpb, tpb>>>(f, x, h0, out, seq, nch);
    }
}

// round 13
// speedup vs baseline: 1.0375x; 1.0375x over previous
#include <cuda_runtime.h>
#include <cstdint>

// ForgetMult fused single-pass chunked scan, decoupled lookback.
// h_t = f_t*x_t + (1-f_t)*h_{t-1}  ==  h_t = h_{t-1} + f_t*(x_t - h_{t-1})
//
// R4-champion structure (many blocks, smem-staged chunk tile) with:
//   - L=16 (128 chunks -> half the lookback-chain hops)
//   - TPB=256 x float2 lanes (64 KB tile, 3 blocks/SM, 24 warps/SM)
//   - acquire/release scoped atomics for flag protocol (no membar.gpu)

#define FM_SEQ     2048
#define FM_NCH     16384
#define FM_NG      (FM_NCH / 2)              // 8192 float2 channel-groups
#define FM_L       16                        // timesteps per chunk
#define FM_NCHUNKS (FM_SEQ / FM_L)           // 128
#define FM_TPB     256                       // threads/block == groups per tile
#define FM_NTILES  (FM_NG / FM_TPB)          // 32
#define FM_NBLK    (FM_NCHUNKS * FM_NTILES)  // 4096

// Scratch (allocation-free rule: __device__ globals). 3 x 8 MB + flags.
__device__ float2 g_pa[FM_NCHUNKS][FM_NG];
__device__ float2 g_pb[FM_NCHUNKS][FM_NG];
__device__ float2 g_inc[FM_NCHUNKS][FM_NG];
__device__ int    g_flag[FM_NCHUNKS][FM_NTILES];  // 0=none, 1=partial, 2=inclusive

__global__ void fm_init_flags()
{
    int i = blockIdx.x * blockDim.x + threadIdx.x;
    if (i < FM_NCHUNKS * FM_NTILES) ((int*)g_flag)[i] = 0;
}

__device__ __forceinline__ void cp_async8(void* s, const void* g)
{
    uint32_t sa = (uint32_t)__cvta_generic_to_shared(s);
    asm volatile("cp.async.ca.shared.global [%0], [%1], 8;\n" :: "r"(sa), "l"(g));
}

__device__ __forceinline__ int ld_acquire_gpu(const int* p)
{
    int v;
    asm volatile("ld.acquire.gpu.global.b32 %0, [%1];" : "=r"(v) : "l"(p) : "memory");
    return v;
}

__device__ __forceinline__ void st_release_gpu(int* p, int v)
{
    asm volatile("st.release.gpu.global.b32 [%0], %1;" :: "l"(p), "r"(v) : "memory");
}

__global__ __launch_bounds__(FM_TPB, 3) void fm_fused(
    const float2* __restrict__ f, const float2* __restrict__ x,
    const float2* __restrict__ h0, float2* __restrict__ out)
{
    // chunk-major bids: lookback waits only on lower block IDs (deadlock-free
    // under in-order dispatch).
    const int chunk = blockIdx.x / FM_NTILES;
    const int tile  = blockIdx.x % FM_NTILES;
    const int tid   = threadIdx.x;
    const int g     = tile * FM_TPB + tid;

    extern __shared__ float2 s_buf[];
    float2* sf = s_buf;                    // [FM_L][FM_TPB]
    float2* sx = s_buf + FM_L * FM_TPB;
    __shared__ int s_stop;

    const size_t base = (size_t)chunk * FM_L * FM_NG + g;

    // ---- Async-load chunk tile. Each thread later reads ONLY slots it wrote,
    // so wait_group alone suffices (no __syncthreads needed here).
#pragma unroll
    for (int t = 0; t < FM_L; t++) {
        cp_async8(&sf[t * FM_TPB + tid], f + base + (size_t)t * FM_NG);
        cp_async8(&sx[t * FM_TPB + tid], x + base + (size_t)t * FM_NG);
    }
    asm volatile("cp.async.commit_group;\n" ::: "memory");
    asm volatile("cp.async.wait_group 0;\n" ::: "memory");

    // ---- Chunk summary: a = prod(1-f), b = local scan from 0.
    float2 a = make_float2(1.f, 1.f);
    float2 b = make_float2(0.f, 0.f);
#pragma unroll
    for (int t = 0; t < FM_L; t++) {
        const float2 ft = sf[t * FM_TPB + tid];
        const float2 xt = sx[t * FM_TPB + tid];
        b.x = fmaf(ft.x, xt.x - b.x, b.x);  a.x *= (1.f - ft.x);
        b.y = fmaf(ft.y, xt.y - b.y, b.y);  a.y *= (1.f - ft.y);
    }

    // ---- Resolve h_start via decoupled lookback (parallel probe).
    float2 hstart;
    if (chunk == 0) {
        hstart = __ldg(h0 + g);
    } else {
        // Publish partial summary; release-store the flag (orders the STGs
        // CTA-wide via the barrier, gpu-wide via .release).
        g_pa[chunk][g] = a;
        g_pb[chunk][g] = b;
        __syncthreads();
        if (tid == 0) st_release_gpu(&g_flag[chunk][tile], 1);

        // Threads probe chunk-1-tid; nearest flag==2 wins via shared atomicMax.
        const int myj = chunk - 1 - tid;
        int stop;
        for (;;) {
            if (tid == 0) s_stop = -1;
            __syncthreads();
            if (tid < 128 && myj >= 0) {
                int s = ld_acquire_gpu(&g_flag[myj][tile]);
                while (s == 0) {
                    __nanosleep(64);
                    s = ld_acquire_gpu(&g_flag[myj][tile]);
                }
                if (s == 2) atomicMax(&s_stop, myj);
            }
            __syncthreads();
            stop = s_stop;
            if (stop >= 0) break;
        }

        // Compose partials (stop+1 .. chunk-1) onto h_end(stop).
        float2 h = g_inc[stop][g];
        for (int j = stop + 1; j < chunk; j++) {
            const float2 aj = g_pa[j][g];
            const float2 bj = g_pb[j][g];
            h.x = fmaf(aj.x, h.x, bj.x);
            h.y = fmaf(aj.y, h.y, bj.y);
        }
        hstart = h;
    }

    // ---- Publish inclusive state ASAP (successors are spinning on it).
    if (chunk < FM_NCHUNKS - 1) {
        float2 he;
        he.x = fmaf(a.x, hstart.x, b.x);
        he.y = fmaf(a.y, hstart.y, b.y);
        g_inc[chunk][g] = he;
        __syncthreads();
        if (tid == 0) st_release_gpu(&g_flag[chunk][tile], 2);
    }

    // ---- Output: exact forward recurrence from smem, streamed stores.
    float2 h = hstart;
#pragma unroll
    for (int t = 0; t < FM_L; t++) {
        const float2 ft = sf[t * FM_TPB + tid];
        const float2 xt = sx[t * FM_TPB + tid];
        h.x = fmaf(ft.x, xt.x - h.x, h.x);
        h.y = fmaf(ft.y, xt.y - h.y, h.y);
        __stcs(out + base + (size_t)t * FM_NG, h);
    }
}

// ---------------- Fallback: naive per-channel scan (unexpected shapes) ----------------
__global__ void fm_naive(const float* __restrict__ f, const float* __restrict__ x,
                         const float* __restrict__ h0, float* __restrict__ out,
                         int seq, int nch)
{
    int c = blockIdx.x * blockDim.x + threadIdx.x;
    if (c >= nch) return;
    float h = h0[c];
    for (int t = 0; t < seq; t++) {
        const float ft = f[(size_t)t * nch + c];
        h = fmaf(1.f - ft, h, ft * x[(size_t)t * nch + c]);
        out[(size_t)t * nch + c] = h;
    }
}

extern "C" void kernel_launch(void* const* d_in, const int* in_sizes, int n_in,
                              void* d_out, int out_size)
{
    const float* f  = (const float*)d_in[0];
    const float* x  = (const float*)d_in[1];
    const float* h0 = (const float*)d_in[2];
    float* out      = (float*)d_out;

    const int nch = in_sizes[2];
    const int seq = in_sizes[0] / nch;

    if (seq == FM_SEQ && nch == FM_NCH) {
        const int smem_bytes = 2 * FM_L * FM_TPB * (int)sizeof(float2);  // 64 KB
        cudaFuncSetAttribute(fm_fused, cudaFuncAttributeMaxDynamicSharedMemorySize,
                             smem_bytes);
        fm_init_flags<<<(FM_NCHUNKS * FM_NTILES + 255) / 256, 256>>>();
        fm_fused<<<FM_NBLK, FM_TPB, smem_bytes>>>(
            (const float2*)f, (const float2*)x, (const float2*)h0, (float2*)out);
    } else {
        int tpb = 128;
        fm_naive<<<(nch + tpb - 1) / tpb, tpb>>>(f, x, h0, out, seq, nch);
    }
}